// round 16
// baseline (speedup 1.0000x reference)
#include <cuda_runtime.h>
#include <cuda_fp16.h>
#include <math.h>
#include <cstdint>

#define Bd 8
#define Nd 2048
#define Cd 768
#define Hd 12
#define HDd 64
// q pre-scale folded with log2(e): 0.125 * 1.44269504088896
#define QSCALEf 0.180336880111112f

// ---------------- scratch ----------------
__device__ __half g_xh[Bd * Nd * Cd];          // fp16 x
__device__ __half g_wh[4][Cd * Cd];            // fp16 weights q,k,v,o
__device__ float  g_lsz[Bd * Nd];              // log2(size)
__device__ __half g_qh[Bd * Hd * Nd * HDd];    // fp16, pre-scaled by 0.125*log2e
__device__ __half g_kh[Bd * Hd * Nd * HDd];
__device__ __half g_vh[Bd * Hd * Nd * HDd];
__device__ __half g_aoh[Bd * Nd * Cd];         // fp16 attention output

// ---------------- helpers ----------------
__device__ __forceinline__ uint32_t smem_u32(const void* p) {
    uint32_t a;
    asm("{ .reg .u64 t; cvta.to.shared.u64 t, %1; cvt.u32.u64 %0, t; }"
        : "=r"(a) : "l"(p));
    return a;
}

__device__ __forceinline__ void mmah(float* c,
                                     unsigned a0, unsigned a1, unsigned a2, unsigned a3,
                                     unsigned b0, unsigned b1) {
    asm volatile(
        "mma.sync.aligned.m16n8k16.row.col.f32.f16.f16.f32 "
        "{%0,%1,%2,%3}, {%4,%5,%6,%7}, {%8,%9}, {%0,%1,%2,%3};"
        : "+f"(c[0]), "+f"(c[1]), "+f"(c[2]), "+f"(c[3])
        : "r"(a0), "r"(a1), "r"(a2), "r"(a3), "r"(b0), "r"(b1));
}

#define LDM_X4(r0, r1, r2, r3, addr) \
    asm volatile("ldmatrix.sync.aligned.m8n8.x4.shared.b16 {%0,%1,%2,%3}, [%4];" \
                 : "=r"(r0), "=r"(r1), "=r"(r2), "=r"(r3) : "r"(addr))

#define LDM_X4T(r0, r1, r2, r3, addr) \
    asm volatile("ldmatrix.sync.aligned.m8n8.x4.trans.shared.b16 {%0,%1,%2,%3}, [%4];" \
                 : "=r"(r0), "=r"(r1), "=r"(r2), "=r"(r3) : "r"(addr))

#define SWZ(x) ((x) ^ (((x) >> 3) & 0x70))

#define CP16(dst, src) \
    asm volatile("cp.async.cg.shared.global [%0], [%1], 16;" \
                 :: "r"(dst), "l"(src) : "memory")
#define CP_COMMIT() asm volatile("cp.async.commit_group;" ::: "memory")
#define CP_WAIT0() asm volatile("cp.async.wait_group 0;" ::: "memory")
#define CP_WAIT1() asm volatile("cp.async.wait_group 1;" ::: "memory")

__device__ __forceinline__ uint32_t packh(float a, float b) {
    __half2 t = __floats2half2_rn(a, b);
    return *reinterpret_cast<uint32_t*>(&t);
}

__device__ __forceinline__ float ex2(float x) {
    float r;
    asm("ex2.approx.ftz.f32 %0, %1;" : "=f"(r) : "f"(x));
    return r;
}

__device__ __forceinline__ float lg2(float x) {
    float r;
    asm("lg2.approx.f32 %0, %1;" : "=f"(r) : "f"(x));
    return r;
}

// ---------------- fused f32 -> f16 convert + log2(size) --------------------
#define NX (Bd * Nd * Cd)
#define NW (Cd * Cd)
#define NS (Bd * Nd)

__global__ __launch_bounds__(256)
void cvt_all_kernel(const float* __restrict__ x,
                    const float* __restrict__ w0, const float* __restrict__ w1,
                    const float* __restrict__ w2, const float* __restrict__ w3,
                    const float* __restrict__ size,
                    __half* __restrict__ xh, __half* __restrict__ wh,
                    float* __restrict__ lsz)
{
    const long long i8 = (long long)(blockIdx.x * 256 + threadIdx.x) * 8;
    if (i8 >= (long long)NX + 4LL * NW) {
        const long long off = i8 - NX - 4LL * NW;
        if (off >= NS) return;
        const float4 a = *(const float4*)(size + off);
        const float4 b = *(const float4*)(size + off + 4);
        float4 la, lb4;
        la.x = lg2(a.x); la.y = lg2(a.y); la.z = lg2(a.z); la.w = lg2(a.w);
        lb4.x = lg2(b.x); lb4.y = lg2(b.y); lb4.z = lg2(b.z); lb4.w = lg2(b.w);
        *(float4*)(lsz + off) = la;
        *(float4*)(lsz + off + 4) = lb4;
        return;
    }
    const float* src;
    __half* dst;
    long long off;
    if (i8 < NX) { src = x; dst = xh; off = i8; }
    else {
        const long long j = i8 - NX;
        const int w = (int)(j / NW);
        off = j - (long long)w * NW;
        src = (w == 0) ? w0 : (w == 1) ? w1 : (w == 2) ? w2 : w3;
        dst = wh + (long long)w * NW;
    }
    const float4 a = *(const float4*)(src + off);
    const float4 b = *(const float4*)(src + off + 4);
    uint4 u;
    u.x = packh(a.x, a.y); u.y = packh(a.z, a.w);
    u.z = packh(b.x, b.y); u.w = packh(b.z, b.w);
    *(uint4*)(dst + off) = u;
}

// ================= fp16 GEMM, cp.async double-buffered (R10 best) ==========
#define GNC (Cd / 64)
#define GSMB 65536

__device__ __forceinline__ void gemm_stage(const __half* __restrict__ Ab,
                                           const __half* __restrict__ Wb,
                                           uint32_t sb, int buf, int tid)
{
    const uint32_t ab = sb + (buf ? 16384u : 0u);
    const uint32_t bb = sb + 32768u + (buf ? 16384u : 0u);
    #pragma unroll
    for (int p = 0; p < 4; p++) {
        const int s = tid + p * 256;
        const int row = s >> 3, seg = s & 7;
        CP16(ab + SWZ(row * 128 + seg * 16), Ab + (size_t)row * Cd + seg * 8);
    }
    #pragma unroll
    for (int p = 0; p < 4; p++) {
        const int s = tid + p * 256;
        const int row = s >> 3, seg = s & 7;
        CP16(bb + SWZ(row * 128 + seg * 16), Wb + (size_t)row * Cd + seg * 8);
    }
}

template <class Epi>
__device__ __forceinline__ void gemm_h2_body(const __half* __restrict__ A,
                                             const __half* __restrict__ W,
                                             int m0, int n0, const Epi& epi)
{
    extern __shared__ char smc[];
    const uint32_t sb = smem_u32(smc);

    const int tid = threadIdx.x, lane = tid & 31, warp = tid >> 5;
    const int wm = warp >> 2, wn = warp & 3;
    const int gid = lane >> 2, tig = lane & 3;

    const int a_row = (lane & 15);
    const int a_bc  = (lane >> 4) << 4;
    const int b_row = (lane & 7) + ((lane >> 4) << 3);
    const int b_bc  = ((lane >> 3) & 1) << 4;

    float acc[4][4][4];
    #pragma unroll
    for (int i = 0; i < 4; i++)
        #pragma unroll
        for (int j = 0; j < 4; j++)
            #pragma unroll
            for (int r = 0; r < 4; r++) acc[i][j][r] = 0.f;

    const __half* Abase = A + (size_t)m0 * Cd;
    const __half* Wbase = W + (size_t)n0 * Cd;

    gemm_stage(Abase, Wbase, sb, 0, tid);
    CP_COMMIT();
    gemm_stage(Abase + 64, Wbase + 64, sb, 1, tid);
    CP_COMMIT();

    for (int c = 0; c < GNC; c++) {
        const int buf = c & 1;
        CP_WAIT1();
        __syncthreads();

        const uint32_t ab = sb + (buf ? 16384u : 0u);
        const uint32_t bb = sb + 32768u + (buf ? 16384u : 0u);
        #pragma unroll
        for (int ks = 0; ks < 4; ks++) {
            uint32_t a[4][4], bk[2][4];
            #pragma unroll
            for (int mi = 0; mi < 4; mi++) {
                const int row = wm * 64 + mi * 16 + a_row;
                LDM_X4(a[mi][0], a[mi][1], a[mi][2], a[mi][3],
                       ab + SWZ(row * 128 + ks * 32 + a_bc));
            }
            #pragma unroll
            for (int nh = 0; nh < 2; nh++) {
                const int row = wn * 32 + nh * 16 + b_row;
                LDM_X4(bk[nh][0], bk[nh][1], bk[nh][2], bk[nh][3],
                       bb + SWZ(row * 128 + ks * 32 + b_bc));
            }
            #pragma unroll
            for (int mi = 0; mi < 4; mi++)
                #pragma unroll
                for (int ni = 0; ni < 4; ni++)
                    mmah(acc[mi][ni], a[mi][0], a[mi][1], a[mi][2], a[mi][3],
                         bk[ni >> 1][(ni & 1) * 2], bk[ni >> 1][(ni & 1) * 2 + 1]);
        }
        __syncthreads();

        if (c + 2 < GNC)
            gemm_stage(Abase + (c + 2) * 64, Wbase + (c + 2) * 64, sb, buf, tid);
        CP_COMMIT();
    }

    #pragma unroll
    for (int mi = 0; mi < 4; mi++)
        #pragma unroll
        for (int ni = 0; ni < 4; ni++)
            epi.emit(wm * 64 + mi * 16 + gid, wn * 32 + ni * 8 + 2 * tig, acc[mi][ni]);
}

struct EpiQKV {
    __half* outb; const float* bias; int m0, n0; float mult;
    __device__ __forceinline__ void emit(int rl, int cl, const float* a) const {
        const int col = n0 + cl;
        const float b0v = bias[col], b1v = bias[col + 1];
        const int h = col >> 6, hd = col & 63;
        #pragma unroll
        for (int hh = 0; hh < 2; hh++) {
            const int r = m0 + rl + hh * 8;
            const int bb = r >> 11, n = r & 2047;
            const size_t idx = (((size_t)(bb * Hd + h)) * Nd + n) * HDd + hd;
            *(uint32_t*)&outb[idx] = packh((a[hh * 2 + 0] + b0v) * mult,
                                           (a[hh * 2 + 1] + b1v) * mult);
        }
    }
};

struct EpiO {
    float* outp; const float* bias; int m0, n0;
    __device__ __forceinline__ void emit(int rl, int cl, const float* a) const {
        const int col = n0 + cl;
        const float b0v = bias[col], b1v = bias[col + 1];
        #pragma unroll
        for (int hh = 0; hh < 2; hh++) {
            const int r = m0 + rl + hh * 8;
            float2 v;
            v.x = a[hh * 2 + 0] + b0v;
            v.y = a[hh * 2 + 1] + b1v;
            *(float2*)&outp[(size_t)r * Cd + col] = v;
        }
    }
};

__global__ __launch_bounds__(256)
void gemm_qkv_h2(const float* __restrict__ bq, const float* __restrict__ bk,
                 const float* __restrict__ bv)
{
    const int z = blockIdx.z;
    const float* bias = (z == 0) ? bq : (z == 1) ? bk : bv;
    __half* outb      = (z == 0) ? g_qh : (z == 1) ? g_kh : g_vh;
    EpiQKV e{outb, bias, (int)blockIdx.y * 128, (int)blockIdx.x * 128,
             (z == 0) ? QSCALEf : 1.0f};
    gemm_h2_body(g_xh, g_wh[z], e.m0, e.n0, e);
}

__global__ __launch_bounds__(256)
void gemm_o_h2(const float* __restrict__ bias, float* __restrict__ out)
{
    EpiO e{out, bias, (int)blockIdx.y * 128, (int)blockIdx.x * 128};
    gemm_h2_body(g_aoh, g_wh[3], e.m0, e.n0, e);
}

// ================= attention: FA2, 128-key chunks, ring-3, Q via slot0 =====
// grid (96, 17): y<16 attention q-tiles; y==16 kmean stride blocks.
// K slots 3x16KB @0; V slots 3x16KB @49152; LB 3x512B @98304. Q staged
// through K slot 0 in the prologue (read once into registers).
// One sync per 128-key chunk (16 chunks) instead of 32.
#define AKS 0
#define AVS 49152
#define ASZ 98304
#define ASMB 99840
#define ANC (Nd / 128)

__global__ __launch_bounds__(256, 2)
void attn_fa2(const float* __restrict__ lszp, float* __restrict__ kmean_out)
{
    extern __shared__ char smc[];
    const uint32_t sb = smem_u32(smc);

    const int tid = threadIdx.x, lane = tid & 31, warp = tid >> 5;

    // ---- fused kmean blocks (y == 16) ----
    if (blockIdx.y == 16) {
        const int stride = 96 * 256;
        for (int i2 = blockIdx.x * 256 + tid; i2 < Bd * Nd * HDd / 2; i2 += stride) {
            const int idx = i2 * 2;
            const int hd = idx & 63;
            const int n  = (idx >> 6) & 2047;
            const int b  = idx >> 17;
            float s0 = 0.f, s1 = 0.f;
            #pragma unroll
            for (int h = 0; h < Hd; h++) {
                const __half2 v = *(const __half2*)
                    &g_kh[(((size_t)(b * Hd + h)) * Nd + n) * HDd + hd];
                const float2 f = __half22float2(v);
                s0 += f.x; s1 += f.y;
            }
            *(float2*)&kmean_out[idx] = make_float2(s0 * (1.0f / Hd), s1 * (1.0f / Hd));
        }
        return;
    }

    const int bh = blockIdx.x;
    const int b = bh / Hd, h = bh % Hd;
    const int q0 = blockIdx.y * 128;
    const int gid = lane >> 2, tig = lane & 3;

    const __half* qb  = g_qh + ((size_t)bh * Nd + q0) * HDd;
    const __half* kbb = g_kh + (size_t)bh * Nd * HDd;
    const __half* vbb = g_vh + (size_t)bh * Nd * HDd;
    const float* lbase = lszp + (size_t)b * Nd;

    // stage one 128-key chunk (K 16KB, V 16KB, lb 512B) into ring slot
    auto stage_kv = [&](int c, int slot) {
        const __half* Kb = kbb + (size_t)c * 128 * HDd;
        const __half* Vb = vbb + (size_t)c * 128 * HDd;
        const uint32_t kdst = sb + AKS + slot * 16384;
        const uint32_t vdst = sb + AVS + slot * 16384;
        #pragma unroll
        for (int p = 0; p < 4; p++) {
            const int s = tid + p * 256;
            const int row = s >> 3, seg = s & 7;
            CP16(kdst + SWZ(row * 128 + seg * 16), Kb + (size_t)row * HDd + seg * 8);
        }
        #pragma unroll
        for (int p = 0; p < 4; p++) {
            const int s = tid + p * 256;
            const int row = s >> 3, seg = s & 7;
            CP16(vdst + SWZ(row * 128 + seg * 16), Vb + (size_t)row * HDd + seg * 8);
        }
        if (tid < 32)
            CP16(sb + ASZ + slot * 512 + tid * 16, lbase + c * 128 + tid * 4);
    };

    const int a_row = (lane & 15);
    const int a_bc  = (lane >> 4) << 4;
    const int b_row = (lane & 7) + ((lane >> 4) << 3);
    const int b_bc  = ((lane >> 3) & 1) << 4;
    const int v_row = (lane & 7) + (((lane >> 3) & 1) << 3);
    const int v_bc  = (lane >> 4) << 4;

    // ---- prologue: Q through K slot 0, read into registers, then free ----
    #pragma unroll
    for (int p = 0; p < 4; p++) {
        const int s = tid + p * 256;
        const int row = s >> 3, seg = s & 7;
        CP16(sb + AKS + SWZ(row * 128 + seg * 16), qb + (size_t)row * HDd + seg * 8);
    }
    CP_COMMIT();
    CP_WAIT0();
    __syncthreads();
    uint32_t qf[4][4];
    #pragma unroll
    for (int ks = 0; ks < 4; ks++) {
        const int row = warp * 16 + a_row;
        LDM_X4(qf[ks][0], qf[ks][1], qf[ks][2], qf[ks][3],
               sb + AKS + SWZ(row * 128 + ks * 32 + a_bc));
    }
    __syncthreads();          // all warps done reading Q before slot 0 reuse

    stage_kv(0, 0);
    CP_COMMIT();
    stage_kv(1, 1);
    CP_COMMIT();

    float acc[8][4];
    #pragma unroll
    for (int i = 0; i < 8; i++)
        #pragma unroll
        for (int r = 0; r < 4; r++) acc[i][r] = 0.f;
    float lsum0 = 0.f, lsum1 = 0.f;

    for (int c = 0; c < ANC; c++) {
        const int slot = c % 3;
        CP_WAIT1();
        __syncthreads();

        // stage chunk c+2 into slot (c+2)%3 == (c-1)%3 (consumed in c-1)
        if (c + 2 < ANC) stage_kv(c + 2, (c + 2) % 3);
        CP_COMMIT();

        const uint32_t kbase = sb + AKS + slot * 16384;
        const uint32_t vbase = sb + AVS + slot * 16384;
        const uint32_t szb   = sb + ASZ + slot * 512;

        #pragma unroll
        for (int hf = 0; hf < 2; hf++) {
            const int rbase = hf * 64;

            // ---- S = Q @ K^T : 8 independent accumulators ----
            float sc[8][4];
            #pragma unroll
            for (int i = 0; i < 8; i++)
                #pragma unroll
                for (int r = 0; r < 4; r++) sc[i][r] = 0.f;

            #pragma unroll
            for (int ks = 0; ks < 4; ks++) {
                uint32_t bk[4][4];
                #pragma unroll
                for (int nh = 0; nh < 4; nh++) {
                    const int row = rbase + nh * 16 + b_row;
                    LDM_X4(bk[nh][0], bk[nh][1], bk[nh][2], bk[nh][3],
                           kbase + SWZ(row * 128 + ks * 32 + b_bc));
                }
                #pragma unroll
                for (int nt = 0; nt < 8; nt++)
                    mmah(sc[nt], qf[ks][0], qf[ks][1], qf[ks][2], qf[ks][3],
                         bk[nt >> 1][(nt & 1) * 2], bk[nt >> 1][(nt & 1) * 2 + 1]);
            }

            // ---- p = ex2(s + lb); pack A fragments; scalar lsum ----
            uint32_t af[4][4];
            #pragma unroll
            for (int nt = 0; nt < 8; nt++) {
                const int col = nt * 8 + 2 * tig;
                float lb0, lb1;
                asm volatile("ld.shared.v2.f32 {%0,%1}, [%2];"
                             : "=f"(lb0), "=f"(lb1)
                             : "r"(szb + (rbase + col) * 4));
                const float p0 = ex2(sc[nt][0] + lb0);
                const float p1 = ex2(sc[nt][1] + lb1);
                const float p2 = ex2(sc[nt][2] + lb0);
                const float p3 = ex2(sc[nt][3] + lb1);
                lsum0 += p0 + p1;
                lsum1 += p2 + p3;
                af[nt >> 1][(nt & 1) * 2 + 0] = packh(p0, p1);
                af[nt >> 1][(nt & 1) * 2 + 1] = packh(p2, p3);
            }

            // ---- O += P @ V ----
            #pragma unroll
            for (int kt = 0; kt < 4; kt++) {
                uint32_t bv[4][4];
                #pragma unroll
                for (int dh = 0; dh < 4; dh++) {
                    const int row = rbase + kt * 16 + v_row;
                    LDM_X4T(bv[dh][0], bv[dh][1], bv[dh][2], bv[dh][3],
                            vbase + SWZ(row * 128 + dh * 32 + v_bc));
                }
                #pragma unroll
                for (int dt = 0; dt < 8; dt++)
                    mmah(acc[dt], af[kt][0], af[kt][1], af[kt][2], af[kt][3],
                         bv[dt >> 1][(dt & 1) * 2], bv[dt >> 1][(dt & 1) * 2 + 1]);
            }
        }
    }

    // ---- reduce l within quad; normalize; store ----
    lsum0 += __shfl_xor_sync(0xFFFFFFFFu, lsum0, 1);
    lsum0 += __shfl_xor_sync(0xFFFFFFFFu, lsum0, 2);
    lsum1 += __shfl_xor_sync(0xFFFFFFFFu, lsum1, 1);
    lsum1 += __shfl_xor_sync(0xFFFFFFFFu, lsum1, 2);
    const float linv0 = 1.f / lsum0;
    const float linv1 = 1.f / lsum1;

    const int r0 = q0 + warp * 16 + gid;
    #pragma unroll
    for (int dt = 0; dt < 8; dt++) {
        const int col = dt * 8 + 2 * tig;
        const size_t o0 = ((size_t)(b * Nd + r0)) * Cd + h * HDd + col;
        const size_t o1 = ((size_t)(b * Nd + r0 + 8)) * Cd + h * HDd + col;
        *(uint32_t*)&g_aoh[o0] = packh(acc[dt][0] * linv0, acc[dt][1] * linv0);
        *(uint32_t*)&g_aoh[o1] = packh(acc[dt][2] * linv1, acc[dt][3] * linv1);
    }
}

// ---------------- launch ----------------------------------------------------
extern "C" void kernel_launch(void* const* d_in, const int* in_sizes, int n_in,
                              void* d_out, int out_size)
{
    const float* x    = (const float*)d_in[0];
    const float* size = (const float*)d_in[1];
    const float* q_w  = (const float*)d_in[2];
    const float* q_b  = (const float*)d_in[3];
    const float* k_w  = (const float*)d_in[4];
    const float* k_b  = (const float*)d_in[5];
    const float* v_w  = (const float*)d_in[6];
    const float* v_b  = (const float*)d_in[7];
    const float* o_w  = (const float*)d_in[8];
    const float* o_b  = (const float*)d_in[9];

    float* out   = (float*)d_out;
    float* kmean = out + (size_t)Bd * Nd * Cd;

    cudaFuncSetAttribute(attn_fa2, cudaFuncAttributeMaxDynamicSharedMemorySize, ASMB);
    cudaFuncSetAttribute(gemm_qkv_h2, cudaFuncAttributeMaxDynamicSharedMemorySize, GSMB);
    cudaFuncSetAttribute(gemm_o_h2, cudaFuncAttributeMaxDynamicSharedMemorySize, GSMB);

    __half* xh_p;  cudaGetSymbolAddress((void**)&xh_p, g_xh);
    __half* wh_p;  cudaGetSymbolAddress((void**)&wh_p, g_wh);
    float*  ls_p;  cudaGetSymbolAddress((void**)&ls_p, g_lsz);

    const long long ntot = (long long)NX + 4LL * NW + NS;
    cvt_all_kernel<<<(unsigned)((ntot / 8 + 255) / 256), 256>>>(
        x, q_w, k_w, v_w, o_w, size, xh_p, wh_p, ls_p);

    dim3 gqkv(Cd / 128, (Bd * Nd) / 128, 3);
    gemm_qkv_h2<<<gqkv, 256, GSMB>>>(q_b, k_b, v_b);

    // attention + fused kmean (y == 16 blocks)
    dim3 gat(Bd * Hd, Nd / 128 + 1);
    attn_fa2<<<gat, 256, ASMB>>>(ls_p, kmean);

    dim3 go(Cd / 128, (Bd * Nd) / 128, 1);
    gemm_o_h2<<<go, 256, GSMB>>>(o_b, out);
}

// round 17
// speedup vs baseline: 1.0908x; 1.0908x over previous
#include <cuda_runtime.h>
#include <cuda_fp16.h>
#include <math.h>
#include <cstdint>

#define Bd 8
#define Nd 2048
#define Cd 768
#define Hd 12
#define HDd 64
// q pre-scale folded with log2(e): 0.125 * 1.44269504088896
#define QSCALEf 0.180336880111112f

// ---------------- scratch ----------------
__device__ __half g_xh[Bd * Nd * Cd];          // fp16 x
__device__ __half g_wh[4][Cd * Cd];            // fp16 weights q,k,v,o
__device__ float  g_lsz[Bd * Nd];              // log2(size)
__device__ __half g_qh[Bd * Hd * Nd * HDd];    // fp16, pre-scaled by 0.125*log2e
__device__ __half g_kh[Bd * Hd * Nd * HDd];
__device__ __half g_vh[Bd * Hd * Nd * HDd];
__device__ __half g_aoh[Bd * Nd * Cd];         // fp16 attention output

// ---------------- helpers ----------------
__device__ __forceinline__ uint32_t smem_u32(const void* p) {
    uint32_t a;
    asm("{ .reg .u64 t; cvta.to.shared.u64 t, %1; cvt.u32.u64 %0, t; }"
        : "=r"(a) : "l"(p));
    return a;
}

__device__ __forceinline__ void mmah(float* c,
                                     unsigned a0, unsigned a1, unsigned a2, unsigned a3,
                                     unsigned b0, unsigned b1) {
    asm volatile(
        "mma.sync.aligned.m16n8k16.row.col.f32.f16.f16.f32 "
        "{%0,%1,%2,%3}, {%4,%5,%6,%7}, {%8,%9}, {%0,%1,%2,%3};"
        : "+f"(c[0]), "+f"(c[1]), "+f"(c[2]), "+f"(c[3])
        : "r"(a0), "r"(a1), "r"(a2), "r"(a3), "r"(b0), "r"(b1));
}

#define LDM_X4(r0, r1, r2, r3, addr) \
    asm volatile("ldmatrix.sync.aligned.m8n8.x4.shared.b16 {%0,%1,%2,%3}, [%4];" \
                 : "=r"(r0), "=r"(r1), "=r"(r2), "=r"(r3) : "r"(addr))

#define LDM_X4T(r0, r1, r2, r3, addr) \
    asm volatile("ldmatrix.sync.aligned.m8n8.x4.trans.shared.b16 {%0,%1,%2,%3}, [%4];" \
                 : "=r"(r0), "=r"(r1), "=r"(r2), "=r"(r3) : "r"(addr))

#define SWZ(x) ((x) ^ (((x) >> 3) & 0x70))

#define CP16(dst, src) \
    asm volatile("cp.async.cg.shared.global [%0], [%1], 16;" \
                 :: "r"(dst), "l"(src) : "memory")
#define CP_COMMIT() asm volatile("cp.async.commit_group;" ::: "memory")
#define CP_WAIT1() asm volatile("cp.async.wait_group 1;" ::: "memory")

__device__ __forceinline__ uint32_t packh(float a, float b) {
    __half2 t = __floats2half2_rn(a, b);
    return *reinterpret_cast<uint32_t*>(&t);
}

__device__ __forceinline__ float ex2(float x) {
    float r;
    asm("ex2.approx.ftz.f32 %0, %1;" : "=f"(r) : "f"(x));
    return r;
}

__device__ __forceinline__ float lg2(float x) {
    float r;
    asm("lg2.approx.f32 %0, %1;" : "=f"(r) : "f"(x));
    return r;
}

// ---------------- fused f32 -> f16 convert + log2(size) --------------------
#define NX (Bd * Nd * Cd)
#define NW (Cd * Cd)
#define NS (Bd * Nd)

__global__ __launch_bounds__(256)
void cvt_all_kernel(const float* __restrict__ x,
                    const float* __restrict__ w0, const float* __restrict__ w1,
                    const float* __restrict__ w2, const float* __restrict__ w3,
                    const float* __restrict__ size,
                    __half* __restrict__ xh, __half* __restrict__ wh,
                    float* __restrict__ lsz)
{
    const long long i8 = (long long)(blockIdx.x * 256 + threadIdx.x) * 8;
    if (i8 >= (long long)NX + 4LL * NW) {
        const long long off = i8 - NX - 4LL * NW;
        if (off >= NS) return;
        const float4 a = *(const float4*)(size + off);
        const float4 b = *(const float4*)(size + off + 4);
        float4 la, lb4;
        la.x = lg2(a.x); la.y = lg2(a.y); la.z = lg2(a.z); la.w = lg2(a.w);
        lb4.x = lg2(b.x); lb4.y = lg2(b.y); lb4.z = lg2(b.z); lb4.w = lg2(b.w);
        *(float4*)(lsz + off) = la;
        *(float4*)(lsz + off + 4) = lb4;
        return;
    }
    const float* src;
    __half* dst;
    long long off;
    if (i8 < NX) { src = x; dst = xh; off = i8; }
    else {
        const long long j = i8 - NX;
        const int w = (int)(j / NW);
        off = j - (long long)w * NW;
        src = (w == 0) ? w0 : (w == 1) ? w1 : (w == 2) ? w2 : w3;
        dst = wh + (long long)w * NW;
    }
    const float4 a = *(const float4*)(src + off);
    const float4 b = *(const float4*)(src + off + 4);
    uint4 u;
    u.x = packh(a.x, a.y); u.y = packh(a.z, a.w);
    u.z = packh(b.x, b.y); u.w = packh(b.z, b.w);
    *(uint4*)(dst + off) = u;
}

// ================= fp16 GEMM: 64x128 tile, 128 thr, 4 CTAs/SM ==============
// Same per-warp math as the 128x128 version (warp tile 64x32, 12 K-chunks,
// double-buffered cp.async) but half the tile -> 48KB smem, 4 CTAs/SM for
// 4-way latency overlap. Bit-identical K-order per output element.
// smem: A0 @0 (8KB), A1 @8192, B0 @16384 (16KB), B1 @32768. total 48KB.
#define GNC (Cd / 64)
#define GSMB 49152

__device__ __forceinline__ void gemm_stage(const __half* __restrict__ Ab,
                                           const __half* __restrict__ Wb,
                                           uint32_t sb, int buf, int tid)
{
    const uint32_t ab = sb + (buf ? 8192u : 0u);
    const uint32_t bb = sb + 16384u + (buf ? 16384u : 0u);
    #pragma unroll
    for (int p = 0; p < 4; p++) {          // A: 64 rows x 128B = 512 segs
        const int s = tid + p * 128;
        const int row = s >> 3, seg = s & 7;
        CP16(ab + SWZ(row * 128 + seg * 16), Ab + (size_t)row * Cd + seg * 8);
    }
    #pragma unroll
    for (int p = 0; p < 8; p++) {          // B: 128 rows x 128B = 1024 segs
        const int s = tid + p * 128;
        const int row = s >> 3, seg = s & 7;
        CP16(bb + SWZ(row * 128 + seg * 16), Wb + (size_t)row * Cd + seg * 8);
    }
}

template <class Epi>
__device__ __forceinline__ void gemm_h3_body(const __half* __restrict__ A,
                                             const __half* __restrict__ W,
                                             int m0, int n0, const Epi& epi)
{
    extern __shared__ char smc[];
    const uint32_t sb = smem_u32(smc);

    const int tid = threadIdx.x, lane = tid & 31, wn = tid >> 5;   // 4 warps
    const int gid = lane >> 2, tig = lane & 3;

    const int a_row = (lane & 15);
    const int a_bc  = (lane >> 4) << 4;
    const int b_row = (lane & 7) + ((lane >> 4) << 3);
    const int b_bc  = ((lane >> 3) & 1) << 4;

    float acc[4][4][4];
    #pragma unroll
    for (int i = 0; i < 4; i++)
        #pragma unroll
        for (int j = 0; j < 4; j++)
            #pragma unroll
            for (int r = 0; r < 4; r++) acc[i][j][r] = 0.f;

    const __half* Abase = A + (size_t)m0 * Cd;
    const __half* Wbase = W + (size_t)n0 * Cd;

    gemm_stage(Abase, Wbase, sb, 0, tid);
    CP_COMMIT();
    gemm_stage(Abase + 64, Wbase + 64, sb, 1, tid);
    CP_COMMIT();

    for (int c = 0; c < GNC; c++) {
        const int buf = c & 1;
        CP_WAIT1();
        __syncthreads();

        const uint32_t ab = sb + (buf ? 8192u : 0u);
        const uint32_t bb = sb + 16384u + (buf ? 16384u : 0u);
        #pragma unroll
        for (int ks = 0; ks < 4; ks++) {
            uint32_t a[4][4], bk[2][4];
            #pragma unroll
            for (int mi = 0; mi < 4; mi++) {
                const int row = mi * 16 + a_row;
                LDM_X4(a[mi][0], a[mi][1], a[mi][2], a[mi][3],
                       ab + SWZ(row * 128 + ks * 32 + a_bc));
            }
            #pragma unroll
            for (int nh = 0; nh < 2; nh++) {
                const int row = wn * 32 + nh * 16 + b_row;
                LDM_X4(bk[nh][0], bk[nh][1], bk[nh][2], bk[nh][3],
                       bb + SWZ(row * 128 + ks * 32 + b_bc));
            }
            #pragma unroll
            for (int mi = 0; mi < 4; mi++)
                #pragma unroll
                for (int ni = 0; ni < 4; ni++)
                    mmah(acc[mi][ni], a[mi][0], a[mi][1], a[mi][2], a[mi][3],
                         bk[ni >> 1][(ni & 1) * 2], bk[ni >> 1][(ni & 1) * 2 + 1]);
        }
        __syncthreads();

        if (c + 2 < GNC)
            gemm_stage(Abase + (c + 2) * 64, Wbase + (c + 2) * 64, sb, buf, tid);
        CP_COMMIT();
    }

    #pragma unroll
    for (int mi = 0; mi < 4; mi++)
        #pragma unroll
        for (int ni = 0; ni < 4; ni++)
            epi.emit(mi * 16 + gid, wn * 32 + ni * 8 + 2 * tig, acc[mi][ni]);
}

struct EpiQKV {
    __half* outb; const float* bias; int m0, n0; float mult;
    __device__ __forceinline__ void emit(int rl, int cl, const float* a) const {
        const int col = n0 + cl;
        const float b0v = bias[col], b1v = bias[col + 1];
        const int h = col >> 6, hd = col & 63;
        #pragma unroll
        for (int hh = 0; hh < 2; hh++) {
            const int r = m0 + rl + hh * 8;
            const int bb = r >> 11, n = r & 2047;
            const size_t idx = (((size_t)(bb * Hd + h)) * Nd + n) * HDd + hd;
            *(uint32_t*)&outb[idx] = packh((a[hh * 2 + 0] + b0v) * mult,
                                           (a[hh * 2 + 1] + b1v) * mult);
        }
    }
};

struct EpiO {
    float* outp; const float* bias; int m0, n0;
    __device__ __forceinline__ void emit(int rl, int cl, const float* a) const {
        const int col = n0 + cl;
        const float b0v = bias[col], b1v = bias[col + 1];
        #pragma unroll
        for (int hh = 0; hh < 2; hh++) {
            const int r = m0 + rl + hh * 8;
            float2 v;
            v.x = a[hh * 2 + 0] + b0v;
            v.y = a[hh * 2 + 1] + b1v;
            *(float2*)&outp[(size_t)r * Cd + col] = v;
        }
    }
};

__global__ __launch_bounds__(128, 4)
void gemm_qkv_h3(const float* __restrict__ bq, const float* __restrict__ bk,
                 const float* __restrict__ bv)
{
    const int z = blockIdx.z;
    const float* bias = (z == 0) ? bq : (z == 1) ? bk : bv;
    __half* outb      = (z == 0) ? g_qh : (z == 1) ? g_kh : g_vh;
    EpiQKV e{outb, bias, (int)blockIdx.y * 64, (int)blockIdx.x * 128,
             (z == 0) ? QSCALEf : 1.0f};
    gemm_h3_body(g_xh, g_wh[z], e.m0, e.n0, e);
}

__global__ __launch_bounds__(128, 4)
void gemm_o_h3(const float* __restrict__ bias, float* __restrict__ out)
{
    EpiO e{out, bias, (int)blockIdx.y * 64, (int)blockIdx.x * 128};
    gemm_h3_body(g_aoh, g_wh[3], e.m0, e.n0, e);
}

// ================= attention: FA2 register-P, 8-wide S accumulators (R15) ==
// grid (96, 17): y<16 attention q-tiles; y==16 kmean stride blocks.
// smem: Q 16KB @0; K ring 3x8KB @16384; V ring 3x8KB @40960; LB 3x256B @65536.
#define AQS 0
#define AKS 16384
#define AVS 40960
#define ASZ 65536
#define ASMB 66304
#define ANC (Nd / 64)

__global__ __launch_bounds__(256, 2)
void attn_fa2(const float* __restrict__ lszp, float* __restrict__ kmean_out)
{
    extern __shared__ char smc[];
    const uint32_t sb = smem_u32(smc);

    const int tid = threadIdx.x, lane = tid & 31, warp = tid >> 5;

    // ---- fused kmean blocks (y == 16) ----
    if (blockIdx.y == 16) {
        const int stride = 96 * 256;
        for (int i2 = blockIdx.x * 256 + tid; i2 < Bd * Nd * HDd / 2; i2 += stride) {
            const int idx = i2 * 2;
            const int hd = idx & 63;
            const int n  = (idx >> 6) & 2047;
            const int b  = idx >> 17;
            float s0 = 0.f, s1 = 0.f;
            #pragma unroll
            for (int h = 0; h < Hd; h++) {
                const __half2 v = *(const __half2*)
                    &g_kh[(((size_t)(b * Hd + h)) * Nd + n) * HDd + hd];
                const float2 f = __half22float2(v);
                s0 += f.x; s1 += f.y;
            }
            *(float2*)&kmean_out[idx] = make_float2(s0 * (1.0f / Hd), s1 * (1.0f / Hd));
        }
        return;
    }

    const int bh = blockIdx.x;
    const int b = bh / Hd, h = bh % Hd;
    const int q0 = blockIdx.y * 128;
    const int gid = lane >> 2, tig = lane & 3;

    const __half* qb  = g_qh + ((size_t)bh * Nd + q0) * HDd;
    const __half* kbb = g_kh + (size_t)bh * Nd * HDd;
    const __half* vbb = g_vh + (size_t)bh * Nd * HDd;
    const float* lbase = lszp + (size_t)b * Nd;

    auto stage_kv = [&](int c, int slot) {
        const __half* Kb = kbb + (size_t)c * 64 * HDd;
        const __half* Vb = vbb + (size_t)c * 64 * HDd;
        const uint32_t kdst = sb + AKS + slot * 8192;
        const uint32_t vdst = sb + AVS + slot * 8192;
        #pragma unroll
        for (int p = 0; p < 2; p++) {
            const int s = tid + p * 256;
            const int row = s >> 3, seg = s & 7;
            CP16(kdst + SWZ(row * 128 + seg * 16), Kb + (size_t)row * HDd + seg * 8);
        }
        #pragma unroll
        for (int p = 0; p < 2; p++) {
            const int s = tid + p * 256;
            const int row = s >> 3, seg = s & 7;
            CP16(vdst + SWZ(row * 128 + seg * 16), Vb + (size_t)row * HDd + seg * 8);
        }
        if (tid < 16)
            CP16(sb + ASZ + slot * 256 + tid * 16, lbase + c * 64 + tid * 4);
    };

    // prologue
    #pragma unroll
    for (int p = 0; p < 4; p++) {
        const int s = tid + p * 256;
        const int row = s >> 3, seg = s & 7;
        CP16(sb + AQS + SWZ(row * 128 + seg * 16), qb + (size_t)row * HDd + seg * 8);
    }
    stage_kv(0, 0);
    CP_COMMIT();
    stage_kv(1, 1);
    CP_COMMIT();

    const int a_row = (lane & 15);
    const int a_bc  = (lane >> 4) << 4;
    const int b_row = (lane & 7) + ((lane >> 4) << 3);
    const int b_bc  = ((lane >> 3) & 1) << 4;
    const int v_row = (lane & 7) + (((lane >> 3) & 1) << 3);
    const int v_bc  = (lane >> 4) << 4;

    CP_WAIT1();
    __syncthreads();
    uint32_t qf[4][4];
    #pragma unroll
    for (int ks = 0; ks < 4; ks++) {
        const int row = warp * 16 + a_row;
        LDM_X4(qf[ks][0], qf[ks][1], qf[ks][2], qf[ks][3],
               sb + AQS + SWZ(row * 128 + ks * 32 + a_bc));
    }

    float acc[8][4];
    #pragma unroll
    for (int i = 0; i < 8; i++)
        #pragma unroll
        for (int r = 0; r < 4; r++) acc[i][r] = 0.f;
    float lsum0 = 0.f, lsum1 = 0.f;

    for (int c = 0; c < ANC; c++) {
        const int slot = c % 3;
        if (c > 0) { CP_WAIT1(); __syncthreads(); }

        if (c + 2 < ANC) stage_kv(c + 2, (c + 2) % 3);
        CP_COMMIT();

        const uint32_t kbase = sb + AKS + slot * 8192;
        const uint32_t vbase = sb + AVS + slot * 8192;
        const uint32_t szb   = sb + ASZ + slot * 256;

        // ---- S = Q @ K^T : 8 independent accumulators ----
        float sc[8][4];
        #pragma unroll
        for (int i = 0; i < 8; i++)
            #pragma unroll
            for (int r = 0; r < 4; r++) sc[i][r] = 0.f;

        #pragma unroll
        for (int ks = 0; ks < 4; ks++) {
            uint32_t bk[4][4];
            #pragma unroll
            for (int nh = 0; nh < 4; nh++) {
                const int row = nh * 16 + b_row;
                LDM_X4(bk[nh][0], bk[nh][1], bk[nh][2], bk[nh][3],
                       kbase + SWZ(row * 128 + ks * 32 + b_bc));
            }
            #pragma unroll
            for (int nt = 0; nt < 8; nt++)
                mmah(sc[nt], qf[ks][0], qf[ks][1], qf[ks][2], qf[ks][3],
                     bk[nt >> 1][(nt & 1) * 2], bk[nt >> 1][(nt & 1) * 2 + 1]);
        }

        // ---- p = ex2(s + lb); pack into A fragments; scalar lsum ----
        uint32_t af[4][4];
        #pragma unroll
        for (int nt = 0; nt < 8; nt++) {
            const int col = nt * 8 + 2 * tig;
            float lb0, lb1;
            asm volatile("ld.shared.v2.f32 {%0,%1}, [%2];"
                         : "=f"(lb0), "=f"(lb1) : "r"(szb + col * 4));
            const float p0 = ex2(sc[nt][0] + lb0);
            const float p1 = ex2(sc[nt][1] + lb1);
            const float p2 = ex2(sc[nt][2] + lb0);
            const float p3 = ex2(sc[nt][3] + lb1);
            lsum0 += p0 + p1;
            lsum1 += p2 + p3;
            af[nt >> 1][(nt & 1) * 2 + 0] = packh(p0, p1);
            af[nt >> 1][(nt & 1) * 2 + 1] = packh(p2, p3);
        }

        // ---- O += P @ V ----
        #pragma unroll
        for (int kt = 0; kt < 4; kt++) {
            uint32_t bv[4][4];
            #pragma unroll
            for (int dh = 0; dh < 4; dh++) {
                const int row = kt * 16 + v_row;
                LDM_X4T(bv[dh][0], bv[dh][1], bv[dh][2], bv[dh][3],
                        vbase + SWZ(row * 128 + dh * 32 + v_bc));
            }
            #pragma unroll
            for (int dt = 0; dt < 8; dt++)
                mmah(acc[dt], af[kt][0], af[kt][1], af[kt][2], af[kt][3],
                     bv[dt >> 1][(dt & 1) * 2], bv[dt >> 1][(dt & 1) * 2 + 1]);
        }
    }

    // ---- reduce l within quad; normalize; store ----
    lsum0 += __shfl_xor_sync(0xFFFFFFFFu, lsum0, 1);
    lsum0 += __shfl_xor_sync(0xFFFFFFFFu, lsum0, 2);
    lsum1 += __shfl_xor_sync(0xFFFFFFFFu, lsum1, 1);
    lsum1 += __shfl_xor_sync(0xFFFFFFFFu, lsum1, 2);
    const float linv0 = 1.f / lsum0;
    const float linv1 = 1.f / lsum1;

    const int r0 = q0 + warp * 16 + gid;
    #pragma unroll
    for (int dt = 0; dt < 8; dt++) {
        const int col = dt * 8 + 2 * tig;
        const size_t o0 = ((size_t)(b * Nd + r0)) * Cd + h * HDd + col;
        const size_t o1 = ((size_t)(b * Nd + r0 + 8)) * Cd + h * HDd + col;
        *(uint32_t*)&g_aoh[o0] = packh(acc[dt][0] * linv0, acc[dt][1] * linv0);
        *(uint32_t*)&g_aoh[o1] = packh(acc[dt][2] * linv1, acc[dt][3] * linv1);
    }
}

// ---------------- launch ----------------------------------------------------
extern "C" void kernel_launch(void* const* d_in, const int* in_sizes, int n_in,
                              void* d_out, int out_size)
{
    const float* x    = (const float*)d_in[0];
    const float* size = (const float*)d_in[1];
    const float* q_w  = (const float*)d_in[2];
    const float* q_b  = (const float*)d_in[3];
    const float* k_w  = (const float*)d_in[4];
    const float* k_b  = (const float*)d_in[5];
    const float* v_w  = (const float*)d_in[6];
    const float* v_b  = (const float*)d_in[7];
    const float* o_w  = (const float*)d_in[8];
    const float* o_b  = (const float*)d_in[9];

    float* out   = (float*)d_out;
    float* kmean = out + (size_t)Bd * Nd * Cd;

    cudaFuncSetAttribute(attn_fa2, cudaFuncAttributeMaxDynamicSharedMemorySize, ASMB);
    cudaFuncSetAttribute(gemm_qkv_h3, cudaFuncAttributeMaxDynamicSharedMemorySize, GSMB);
    cudaFuncSetAttribute(gemm_o_h3, cudaFuncAttributeMaxDynamicSharedMemorySize, GSMB);

    __half* xh_p;  cudaGetSymbolAddress((void**)&xh_p, g_xh);
    __half* wh_p;  cudaGetSymbolAddress((void**)&wh_p, g_wh);
    float*  ls_p;  cudaGetSymbolAddress((void**)&ls_p, g_lsz);

    const long long ntot = (long long)NX + 4LL * NW + NS;
    cvt_all_kernel<<<(unsigned)((ntot / 8 + 255) / 256), 256>>>(
        x, q_w, k_w, v_w, o_w, size, xh_p, wh_p, ls_p);

    dim3 gqkv(Cd / 128, (Bd * Nd) / 64, 3);
    gemm_qkv_h3<<<gqkv, 128, GSMB>>>(q_b, k_b, v_b);

    // attention + fused kmean (y == 16 blocks)
    dim3 gat(Bd * Hd, Nd / 128 + 1);
    attn_fa2<<<gat, 256, ASMB>>>(ls_p, kmean);

    dim3 go(Cd / 128, (Bd * Nd) / 64, 1);
    gemm_o_h3<<<go, 128, GSMB>>>(o_b, out);
}